// round 11
// baseline (speedup 1.0000x reference)
#include <cuda_runtime.h>
#include <math.h>

#define BATCH 64
#define IMH 512
#define IMW 512
#define NC 64
#define NORI 9
#define NB 63
#define OUT_PER_B (NB*NB*2*2*NORI)   // 142884
#define NPOS (NB*NB)                 // 3969

// Transposed cell histogram scratch: [B][9][NC][NC] = 9.4 MB (L2-resident)
__device__ float g_hist[(size_t)BATCH * NORI * NC * NC];

__device__ __forceinline__ float fsqrt_approx(float v) {
    float r;
    asm("sqrt.approx.f32 %0, %1;" : "=f"(r) : "f"(v));
    return r;
}

// ---------------------------------------------------------------------------
// Kernel 1: gray -> gradients -> orientation cumsum -> 8x8 cell histograms
// Tile = 64x64 pixels (8x8 cells), 256 threads, two compute phases of the
// proven 2x4-patch structure. 5 CTAs/SM; halo overhead 260px/tile (was 392
// for same area); half the CTAs -> amortized prologue.
// ---------------------------------------------------------------------------
__global__ __launch_bounds__(256, 5) void hog_cells_kernel(const float* __restrict__ x)
{
    __shared__ float sm[66][68];        // 66x66 gray halo tile, padded stride
    __shared__ float shist[NORI][64];   // per-cell hist staging (8x8 cells)

    const int bx = blockIdx.x;          // 0..7
    const int by = blockIdx.y;          // 0..7
    const int b  = blockIdx.z;
    const int tid = threadIdx.x;
    const int oy = by * 64;
    const int ox = bx * 64;

    // ---- interior 64x64 gray: 2 halves x (6x LDG.128 -> 8 pixels) ----
#pragma unroll
    for (int half = 0; half < 2; half++) {
        const int idxA = half * 512 + tid;        // 0..1023
        const int rowA = idxA >> 4;               // 0..63
        const int gA   = idxA & 15;
        const int rowB = (idxA + 256) >> 4;
        const size_t offA = ((size_t)((b * IMH) + oy + rowA) * IMW + ox + gA * 4) * 3;
        const size_t offB = ((size_t)((b * IMH) + oy + rowB) * IMW + ox + gA * 4) * 3;
        const float4* pA = reinterpret_cast<const float4*>(x + offA);
        const float4* pB = reinterpret_cast<const float4*>(x + offB);
        const float4 a0 = pA[0], a1 = pA[1], a2 = pA[2];
        const float4 b0 = pB[0], b1 = pB[1], b2 = pB[2];
        float* d = &sm[rowA + 1][gA * 4 + 1];
        d[0] = 0.2125f * a0.x + 0.7154f * a0.y + 0.0721f * a0.z;
        d[1] = 0.2125f * a0.w + 0.7154f * a1.x + 0.0721f * a1.y;
        d[2] = 0.2125f * a1.z + 0.7154f * a1.w + 0.0721f * a2.x;
        d[3] = 0.2125f * a2.y + 0.7154f * a2.z + 0.0721f * a2.w;
        float* e = &sm[rowB + 1][gA * 4 + 1];
        e[0] = 0.2125f * b0.x + 0.7154f * b0.y + 0.0721f * b0.z;
        e[1] = 0.2125f * b0.w + 0.7154f * b1.x + 0.0721f * b1.y;
        e[2] = 0.2125f * b1.z + 0.7154f * b1.w + 0.0721f * b2.x;
        e[3] = 0.2125f * b2.y + 0.7154f * b2.z + 0.0721f * b2.w;
    }

    // ---- halo ring: 260 px on the 66x66 border (mirror at image borders) ----
    // element e -> (lr,lc):  top 0..65, bottom 66..131, left 132..195, right 196..259
    {
#pragma unroll
        for (int pass = 0; pass < 2; pass++) {
            const int e = (pass == 0) ? tid : 256 + tid;
            if (pass == 0 || tid < 4) {
                int lr, lc;
                if (e < 66)       { lr = 0;        lc = e;       }
                else if (e < 132) { lr = 65;       lc = e - 66;  }
                else if (e < 196) { lr = e - 131;  lc = 0;       }
                else              { lr = e - 195;  lc = 65;      }
                int hh = oy - 1 + lr;
                int hw = ox - 1 + lc;
                hh = (hh < 0) ? 1 : ((hh > IMH - 1) ? IMH - 2 : hh);
                hw = (hw < 0) ? 1 : ((hw > IMW - 1) ? IMW - 2 : hw);
                const float* p = x + ((size_t)(b * IMH + hh) * IMW + hw) * 3;
                sm[lr][lc] = 0.2125f * p[0] + 0.7154f * p[1] + 0.0721f * p[2];
            }
        }
    }
    __syncthreads();

    // ---- 2 compute phases; each: 2x4 pixel patch per thread ----
    const int cell = tid >> 3;          // 0..31  (4 cell-rows x 8 cols per phase)
    const int sub  = tid & 7;
    const int pxb = (cell & 7) * 8 + (sub & 1) * 4;     // multiple of 4
    const int pyb = (cell >> 3) * 8 + (sub >> 1) * 2;   // 2-row band base

#pragma unroll
    for (int ph = 0; ph < 2; ph++) {
        const int py0 = pyb + ph * 32;

        // 4x6 gray patch via 4x (LDS.128 + LDS.64)
        float P[4][6];
#pragma unroll
        for (int r = 0; r < 4; r++) {
            const float4 a = *reinterpret_cast<const float4*>(&sm[py0 + r][pxb]);
            const float2 e = *reinterpret_cast<const float2*>(&sm[py0 + r][pxb + 4]);
            P[r][0] = a.x; P[r][1] = a.y; P[r][2] = a.z; P[r][3] = a.w;
            P[r][4] = e.x; P[r][5] = e.y;
        }

        float c[NORI];
#pragma unroll
        for (int o = 0; o < NORI; o++) c[o] = 0.0f;

#pragma unroll
        for (int dy = 0; dy < 2; dy++) {
#pragma unroll
            for (int dx = 0; dx < 4; dx++) {
                const float gr = P[dy + 2][dx + 1] - P[dy][dx + 1];
                const float gc = P[dy + 1][dx + 2] - P[dy + 1][dx];
                const float mag = fsqrt_approx(gr * gr + gc * gc);

                // canonicalize to theta in [0,180)
                const bool flip = (gr < 0.0f) || (gr == 0.0f && gc < 0.0f);
                const float yy = flip ? -gr : gr;
                const float xx = flip ? -gc : gc;

                // shared products: xa_k = xx*sin(20k); s_k = xa_k -/+ yy*cos(20k)
                const float xa1 = xx * 0.3420201433f;
                const float xa2 = xx * 0.6427876097f;
                const float xa3 = xx * 0.8660254038f;
                const float xa4 = xx * 0.9848077530f;
                const float s1 = xa1 - yy * 0.9396926208f;
                const float s8 = xa1 + yy * 0.9396926208f;
                const float s2 = xa2 - yy * 0.7660444431f;
                const float s7 = xa2 + yy * 0.7660444431f;
                const float s3 = xa3 - yy * 0.5000000000f;
                const float s6 = xa3 + yy * 0.5000000000f;
                const float s4 = xa4 - yy * 0.1736481777f;
                const float s5 = xa4 + yy * 0.1736481777f;

                c[0] += mag;
                if (s1 < 0.0f) c[1] += mag;
                if (s2 < 0.0f) c[2] += mag;
                if (s3 < 0.0f) c[3] += mag;
                if (s4 < 0.0f) c[4] += mag;
                if (s5 < 0.0f) c[5] += mag;
                if (s6 < 0.0f) c[6] += mag;
                if (s7 < 0.0f) c[7] += mag;
                if (s8 < 0.0f) c[8] += mag;
            }
        }

        // reduce 8 patch threads per cell (consecutive lanes)
#pragma unroll
        for (int o = 0; o < NORI; o++) {
            c[o] += __shfl_xor_sync(0xffffffffu, c[o], 1);
            c[o] += __shfl_xor_sync(0xffffffffu, c[o], 2);
            c[o] += __shfl_xor_sync(0xffffffffu, c[o], 4);
        }

        if (sub == 0) {
            const int sc = ph * 32 + cell;      // 0..63
#pragma unroll
            for (int o = 0; o < NORI - 1; o++)
                shist[o][sc] = (c[o] - c[o + 1]) * 0.015625f;
            shist[NORI - 1][sc] = c[NORI - 1] * 0.015625f;
        }
    }
    __syncthreads();

    // ---- transposed global store: g_hist[b][o][cellY][cellX] ----
    const size_t base = (size_t)b * NORI * NC * NC;
    for (int i = tid; i < NORI * 64; i += 256) {
        const int o   = i >> 6;
        const int cl  = i & 63;
        g_hist[base + (size_t)o * (NC * NC) + (by * 8 + (cl >> 3)) * NC + (bx * 8 + (cl & 7))]
            = shist[o][cl];
    }
}

// ---------------------------------------------------------------------------
// Kernel 2: 4 threads per block position, array-free scalars, shfl-reduced
// norms, conflict-free smem staging, float4 coalesced out. (unchanged)
// ---------------------------------------------------------------------------
__global__ __launch_bounds__(256) void hog_blocks_kernel(float* __restrict__ out)
{
    __shared__ float buf[64 * 36];

    const int b   = blockIdx.y;
    const int p0  = blockIdx.x * 64;
    const int tid = threadIdx.x;

    const int lp = tid >> 2;
    const int q  = tid & 3;
    const int p  = p0 + lp;
    const bool valid = (p < NPOS);
    const int pc = valid ? p : NPOS - 1;
    const int rp = pc / NB;
    const int cp = pc - rp * NB;
    const int dr = q >> 1;
    const int dc = q & 1;

    const float* hp = g_hist + (size_t)b * NORI * NC * NC + (rp + dr) * NC + (cp + dc);

    const float v0 = hp[0 * 4096];
    const float v1 = hp[1 * 4096];
    const float v2 = hp[2 * 4096];
    const float v3 = hp[3 * 4096];
    const float v4 = hp[4 * 4096];
    const float v5 = hp[5 * 4096];
    const float v6 = hp[6 * 4096];
    const float v7 = hp[7 * 4096];
    const float v8 = hp[8 * 4096];

    float ss = 0.25e-10f;
    ss = fmaf(v0, v0, ss); ss = fmaf(v1, v1, ss); ss = fmaf(v2, v2, ss);
    ss = fmaf(v3, v3, ss); ss = fmaf(v4, v4, ss); ss = fmaf(v5, v5, ss);
    ss = fmaf(v6, v6, ss); ss = fmaf(v7, v7, ss); ss = fmaf(v8, v8, ss);
    ss += __shfl_xor_sync(0xffffffffu, ss, 1);
    ss += __shfl_xor_sync(0xffffffffu, ss, 2);

    const float n1 = rsqrtf(ss);
    const float w0 = fminf(v0 * n1, 0.2f);
    const float w1 = fminf(v1 * n1, 0.2f);
    const float w2 = fminf(v2 * n1, 0.2f);
    const float w3 = fminf(v3 * n1, 0.2f);
    const float w4 = fminf(v4 * n1, 0.2f);
    const float w5 = fminf(v5 * n1, 0.2f);
    const float w6 = fminf(v6 * n1, 0.2f);
    const float w7 = fminf(v7 * n1, 0.2f);
    const float w8 = fminf(v8 * n1, 0.2f);

    float ss2 = 0.25e-10f;
    ss2 = fmaf(w0, w0, ss2); ss2 = fmaf(w1, w1, ss2); ss2 = fmaf(w2, w2, ss2);
    ss2 = fmaf(w3, w3, ss2); ss2 = fmaf(w4, w4, ss2); ss2 = fmaf(w5, w5, ss2);
    ss2 = fmaf(w6, w6, ss2); ss2 = fmaf(w7, w7, ss2); ss2 = fmaf(w8, w8, ss2);
    ss2 += __shfl_xor_sync(0xffffffffu, ss2, 1);
    ss2 += __shfl_xor_sync(0xffffffffu, ss2, 2);

    const float n2 = rsqrtf(ss2);
    if (valid) {
        float* d = &buf[lp * 36 + q * NORI];
        d[0] = w0 * n2; d[1] = w1 * n2; d[2] = w2 * n2;
        d[3] = w3 * n2; d[4] = w4 * n2; d[5] = w5 * n2;
        d[6] = w6 * n2; d[7] = w7 * n2; d[8] = w8 * n2;
    }
    __syncthreads();

    const int npos = min(64, NPOS - p0);
    const int n4 = npos * 9;
    const float4* s4 = reinterpret_cast<const float4*>(buf);
    float4* o4 = reinterpret_cast<float4*>(out + (size_t)b * OUT_PER_B + (size_t)p0 * 36);
    for (int i = tid; i < n4; i += 256)
        o4[i] = s4[i];
}

extern "C" void kernel_launch(void* const* d_in, const int* in_sizes, int n_in,
                              void* d_out, int out_size)
{
    const float* x = (const float*)d_in[0];
    float* out = (float*)d_out;

    dim3 g1(IMW / 64, IMH / 64, BATCH);          // (8, 8, 64) = 4096 CTAs
    hog_cells_kernel<<<g1, 256>>>(x);

    dim3 g2((NPOS + 63) / 64, BATCH);            // (63, 64)
    hog_blocks_kernel<<<g2, 256>>>(out);
}